// round 16
// baseline (speedup 1.0000x reference)
#include <cuda_runtime.h>

#define BB 2048
#define TT 512
#define DD 32
#define HH 16
typedef unsigned long long u64;

// Scratch (device globals: allocation-guard-safe)
__device__ __align__(16) float g_x[(size_t)TT * BB * HH];   // pre-net output, [t][b][h]
__device__ __align__(16) float g_h[BB * HH];
__device__ __align__(16) float g_c[BB * HH];

__device__ __forceinline__ float ex2f_(float x){ float y; asm("ex2.approx.f32 %0, %1;" : "=f"(y) : "f"(x)); return y; }
__device__ __forceinline__ float rcpf_(float x){ float y; asm("rcp.approx.f32 %0, %1;" : "=f"(y) : "f"(x)); return y; }

#define L2E 1.4426950408889634f

// v = 1 - m * rcp(1 + 2^(s*x)) : sigmoid (s=L2E,m=1), tanh (s=2*L2E,m=2)
__device__ __forceinline__ float gate_act(float x, float s, float m){
    return fmaf(-m, rcpf_(1.0f + ex2f_(s * x)), 1.0f);
}

// ---- f32x2 packed helpers ----
__device__ __forceinline__ u64 pack2(float lo, float hi){ u64 r; asm("mov.b64 %0, {%1,%2};" : "=l"(r) : "f"(lo), "f"(hi)); return r; }
__device__ __forceinline__ u64 dup2(float v){ u64 r; asm("mov.b64 %0, {%1,%1};" : "=l"(r) : "f"(v)); return r; }
__device__ __forceinline__ void unpack2(u64 v, float& lo, float& hi){ asm("mov.b64 {%0,%1}, %2;" : "=f"(lo), "=f"(hi) : "l"(v)); }
__device__ __forceinline__ u64 fma2(u64 a, u64 b, u64 c){ u64 d; asm("fma.rn.f32x2 %0, %1, %2, %3;" : "=l"(d) : "l"(a), "l"(b), "l"(c)); return d; }
__device__ __forceinline__ u64 add2(u64 a, u64 b){ u64 d; asm("add.rn.f32x2 %0, %1, %2;" : "=l"(d) : "l"(a), "l"(b)); return d; }
__device__ __forceinline__ float hsum2(u64 a){ float lo, hi; unpack2(a, lo, hi); return lo + hi; }
__device__ __forceinline__ u64 leaky2(u64 a){
    float lo, hi; unpack2(a, lo, hi);
    lo = fmaxf(lo, 0.01f*lo); hi = fmaxf(hi, 0.01f*hi);
    return pack2(lo, hi);
}

// Broadcast a per-lane scalar (lane k and k+16 hold v[k]) into 8 packed pairs.
// Pure shuffles: no smem, no syncwarp. Last value ready ~45 cyc, pipelined.
__device__ __forceinline__ void bcast16(float v, u64 (&P)[8]){
#pragma unroll
    for (int j = 0; j < 8; j++){
        float e0 = __shfl_sync(0xffffffffu, v, 2*j);
        float e1 = __shfl_sync(0xffffffffu, v, 2*j+1);
        P[j] = pack2(e0, e1);
    }
}

// ---------------------------------------------------------------------------
// Kernel 1: pre-net (85us). 2 rows/thread batch-packed f32x2, scalar smem
// weights (LDS.32 broadcast), k chunked.
// ---------------------------------------------------------------------------
__global__ __launch_bounds__(256) void prenet_kernel(
    const float* __restrict__ seq,
    const float* __restrict__ w1, const float* __restrict__ b1,
    const float* __restrict__ w2, const float* __restrict__ b2,
    const float* __restrict__ w3, const float* __restrict__ b3)
{
    __shared__ float sw1[HH*DD], sw2[HH*HH], sw3[HH*HH], sb[3*HH];
    int tid = threadIdx.x;
    for (int i = tid; i < HH*DD; i += 256) sw1[i] = w1[i];
    for (int i = tid; i < HH*HH; i += 256){ sw2[i] = w2[i]; sw3[i] = w3[i]; }
    if (tid < HH){ sb[tid] = b1[tid]; sb[HH+tid] = b2[tid]; sb[2*HH+tid] = b3[tid]; }
    __syncthreads();

    int r = blockIdx.x * 256 + tid;
    int b = r & (BB - 1);
    int t = r >> 11;

    const float4* rA = reinterpret_cast<const float4*>(seq + ((size_t)b*TT + t)*DD);
    const float4* rB = reinterpret_cast<const float4*>(seq + ((size_t)b*TT + t + 256)*DD);

    u64 acc[HH];
#pragma unroll
    for (int j = 0; j < HH; j++) acc[j] = dup2(sb[j]);

#pragma unroll
    for (int kc = 0; kc < 2; kc++){
        u64 inP[16];
#pragma unroll
        for (int i = 0; i < 4; i++){
            float4 a = rA[kc*4 + i], c = rB[kc*4 + i];
            inP[4*i+0] = pack2(a.x, c.x); inP[4*i+1] = pack2(a.y, c.y);
            inP[4*i+2] = pack2(a.z, c.z); inP[4*i+3] = pack2(a.w, c.w);
        }
#pragma unroll
        for (int j = 0; j < HH; j++){
            const float* wr = &sw1[j*DD + kc*16];
            u64 a = acc[j];
#pragma unroll
            for (int k = 0; k < 16; k++) a = fma2(dup2(wr[k]), inP[k], a);
            acc[j] = a;
        }
    }
    u64 y1[HH];
#pragma unroll
    for (int j = 0; j < HH; j++) y1[j] = leaky2(acc[j]);

#pragma unroll
    for (int j = 0; j < HH; j++){
        const float* wr = &sw2[j*HH];
        u64 a = dup2(sb[HH+j]);
#pragma unroll
        for (int k = 0; k < HH; k++) a = fma2(dup2(wr[k]), y1[k], a);
        acc[j] = a;
    }
    u64 y2[HH];
#pragma unroll
    for (int j = 0; j < HH; j++) y2[j] = leaky2(acc[j]);

    float ya[HH], yb[HH];
#pragma unroll
    for (int j = 0; j < HH; j++){
        const float* wr = &sw3[j*HH];
        u64 a = dup2(sb[2*HH+j]);
#pragma unroll
        for (int k = 0; k < HH; k++) a = fma2(dup2(wr[k]), y2[k], a);
        unpack2(a, ya[j], yb[j]);
    }

    float4* xa = reinterpret_cast<float4*>(g_x + ((size_t)t*BB + b)*HH);
    float4* xb = reinterpret_cast<float4*>(g_x + ((size_t)(t+256)*BB + b)*HH);
#pragma unroll
    for (int i = 0; i < 4; i++){
        xa[i] = make_float4(ya[4*i], ya[4*i+1], ya[4*i+2], ya[4*i+3]);
        xb[i] = make_float4(yb[4*i], yb[4*i+1], yb[4*i+2], yb[4*i+3]);
    }
}

// ---------------------------------------------------------------------------
// Kernel 2: encoder LSTM. 1 elem/warp, 128-thr CTAs (SMSP-balanced), ZERO smem
// in the loop: h broadcast by 16 shfl.idx (all lanes hold correct h since the
// symmetric update), x prefetched from gmem/L2.
// ---------------------------------------------------------------------------
__global__ __launch_bounds__(128) void encoder_kernel(
    const float* __restrict__ Wih, const float* __restrict__ Whh,
    const float* __restrict__ bih, const float* __restrict__ bhh)
{
    int tid  = threadIdx.x;
    int w    = tid >> 5, lane = tid & 31;
    int g    = lane & 15, half = lane >> 4;
    int b    = blockIdx.x * 4 + w;

    int r0 = half ? (2*HH + g) : g;          // i (low) / g (high)
    int r1 = half ? (3*HH + g) : (HH + g);   // f (low) / o (high)

    u64 wiP0[8], wiP1[8], whP0[8], whP1[8];
    {
        const ulonglong2* p0 = reinterpret_cast<const ulonglong2*>(Wih + r0*HH);
        const ulonglong2* p1 = reinterpret_cast<const ulonglong2*>(Wih + r1*HH);
        const ulonglong2* q0 = reinterpret_cast<const ulonglong2*>(Whh + r0*HH);
        const ulonglong2* q1 = reinterpret_cast<const ulonglong2*>(Whh + r1*HH);
#pragma unroll
        for (int i = 0; i < 4; i++){
            ulonglong2 v;
            v = p0[i]; wiP0[2*i] = v.x; wiP0[2*i+1] = v.y;
            v = p1[i]; wiP1[2*i] = v.x; wiP1[2*i+1] = v.y;
            v = q0[i]; whP0[2*i] = v.x; whP0[2*i+1] = v.y;
            v = q1[i]; whP1[2*i] = v.x; whP1[2*i+1] = v.y;
        }
    }
    u64 bg0P = pack2(bih[r0] + bhh[r0], 0.0f);
    u64 bg1P = pack2(bih[r1] + bhh[r1], 0.0f);
    float s0 = half ? 2.0f*L2E : L2E;
    float m0 = half ? 2.0f : 1.0f;

    float c = 0.0f, h = 0.0f;

    u64 xP[8];
    {
        const ulonglong2* p = reinterpret_cast<const ulonglong2*>(g_x + (size_t)b*HH);
#pragma unroll
        for (int i = 0; i < 4; i++){ ulonglong2 v = p[i]; xP[2*i] = v.x; xP[2*i+1] = v.y; }
    }

#pragma unroll 1
    for (int t = 0; t < TT; t++){
        u64 hP[8];
        bcast16(h, hP);                    // 16 SHFL + 8 MOV, no sync/smem

        u64 pA = bg0P, qA = 0ULL, pB = bg1P, qB = 0ULL;
#pragma unroll
        for (int i = 0; i < 4; i++){
            pA = fma2(whP0[2*i],   hP[2*i],   pA);
            qA = fma2(whP0[2*i+1], hP[2*i+1], qA);
            pB = fma2(whP1[2*i],   hP[2*i],   pB);
            qB = fma2(whP1[2*i+1], hP[2*i+1], qB);
            pA = fma2(wiP0[2*i],   xP[2*i],   pA);
            qA = fma2(wiP0[2*i+1], xP[2*i+1], qA);
            pB = fma2(wiP1[2*i],   xP[2*i],   pB);
            qB = fma2(wiP1[2*i+1], xP[2*i+1], qB);
        }
        // prefetch next x (xP dead after accum)
        {
            int tn = (t + 1 < TT) ? t + 1 : t;
            const ulonglong2* pn = reinterpret_cast<const ulonglong2*>(g_x + ((size_t)tn*BB + b)*HH);
#pragma unroll
            for (int i = 0; i < 4; i++){ ulonglong2 v = pn[i]; xP[2*i] = v.x; xP[2*i+1] = v.y; }
        }
        float a0 = hsum2(add2(pA, qA));
        float a1 = hsum2(add2(pB, qB));
        float v0 = gate_act(a0, s0, m0);          // i / g
        float v1 = gate_act(a1, L2E, 1.0f);       // f / o
        float gg = __shfl_xor_sync(0xffffffffu, v0, 16);
        float oo = __shfl_xor_sync(0xffffffffu, v1, 16);
        float cf = half ? oo : v1;                // f on every lane (SEL)
        float ho = half ? v1 : oo;                // o on every lane (SEL)
        c = fmaf(cf, c, v0 * gg);
        h = ho * gate_act(c, 2.0f*L2E, 2.0f);
    }
    if (!half){ g_h[b*HH + g] = h; g_c[b*HH + g] = c; }
}

// ---------------------------------------------------------------------------
// Kernel 3: decoder. 1 elem/warp + W2-fusion + shfl-only state movement:
// h and s1 broadcast by shuffles; loop touches smem only for the constant
// w1/post rows (off-chain, conflict-free stride-9). No syncwarp in the loop.
// ---------------------------------------------------------------------------
__global__ __launch_bounds__(128) void decoder_kernel(
    const float* __restrict__ Wih, const float* __restrict__ Whh,
    const float* __restrict__ bih, const float* __restrict__ bhh,
    const float* __restrict__ h2l_w1, const float* __restrict__ h2l_b1,
    const float* __restrict__ h2l_w2, const float* __restrict__ h2l_b2,
    const float* __restrict__ post_w, const float* __restrict__ post_b,
    float* __restrict__ out, int dup)
{
    __shared__ __align__(16) u64 w1p[HH*9];       // h2l_w1 k-packed, row stride 9
    __shared__ __align__(16) u64 postp[DD*9];     // post_w k-packed, row stride 9
    __shared__ float W2s[HH*HH];
    __shared__ float b2s[HH];

    int tid = threadIdx.x;
    for (int i = tid; i < HH*8; i += 128){
        int j = i >> 3, k = i & 7;
        w1p[j*9+k] = pack2(h2l_w1[j*HH+2*k], h2l_w1[j*HH+2*k+1]);
    }
    for (int i = tid; i < DD*8; i += 128){
        int d = i >> 3, k = i & 7;
        postp[d*9+k] = pack2(post_w[d*HH+2*k], post_w[d*HH+2*k+1]);
    }
    for (int i = tid; i < HH*HH; i += 128) W2s[i] = h2l_w2[i];
    if (tid < HH) b2s[tid] = h2l_b2[tid];
    __syncthreads();

    int w    = tid >> 5, lane = tid & 31;
    int g    = lane & 15, half = lane >> 4;
    int b    = blockIdx.x * 4 + w;

    int r0 = half ? (2*HH + g) : g;
    int r1 = half ? (3*HH + g) : (HH + g);

    u64 wiP0[8], wiP1[8], whP0[8], whP1[8];
    {
        const ulonglong2* p0 = reinterpret_cast<const ulonglong2*>(Wih + r0*HH);
        const ulonglong2* p1 = reinterpret_cast<const ulonglong2*>(Wih + r1*HH);
        const ulonglong2* q0 = reinterpret_cast<const ulonglong2*>(Whh + r0*HH);
        const ulonglong2* q1 = reinterpret_cast<const ulonglong2*>(Whh + r1*HH);
#pragma unroll
        for (int i = 0; i < 4; i++){
            ulonglong2 v;
            v = p0[i]; wiP0[2*i] = v.x; wiP0[2*i+1] = v.y;
            v = p1[i]; wiP1[2*i] = v.x; wiP1[2*i+1] = v.y;
            v = q0[i]; whP0[2*i] = v.x; whP0[2*i+1] = v.y;
            v = q1[i]; whP1[2*i] = v.x; whP1[2*i+1] = v.y;
        }
    }
    float bS0 = bih[r0] + bhh[r0];
    float bS1 = bih[r1] + bhh[r1];
    u64 bg0P = pack2(bS0, 0.0f);
    u64 bg1P = pack2(bS1, 0.0f);
    float s0 = half ? 2.0f*L2E : L2E;
    float m0 = half ? 2.0f : 1.0f;
    float pb  = post_b[lane];
    float hb1v = h2l_b1[g];

    float c  = g_c[b*HH + g];
    float h  = g_h[b*HH + g];                              // same value on lane g and g+16
    float sv = g_x[((size_t)(TT-1)*BB + b)*HH + g];        // start0, per-lane

    u64 hP[8], svP[8];
    bcast16(h, hP);
    bcast16(sv, svP);

    float* outp = out + (size_t)b*TT*DD + lane;
    const size_t dupoff = dup ? (size_t)BB*TT*DD : 0;      // dup=0 -> benign double store
    const u64* w1r = &w1p[g*9];
    const u64* pwr = &postp[lane*9];

    // gates from (svP, hP) -> new c, h (all lanes correct; branch-free)
    auto gates = [&](){
        u64 pA = bg0P, qA = 0ULL, pB = bg1P, qB = 0ULL;
#pragma unroll
        for (int i = 0; i < 4; i++){
            pA = fma2(wiP0[2*i],   svP[2*i],   pA);
            qA = fma2(wiP0[2*i+1], svP[2*i+1], qA);
            pB = fma2(wiP1[2*i],   svP[2*i],   pB);
            qB = fma2(wiP1[2*i+1], svP[2*i+1], qB);
            pA = fma2(whP0[2*i],   hP[2*i],    pA);
            qA = fma2(whP0[2*i+1], hP[2*i+1],  qA);
            pB = fma2(whP1[2*i],   hP[2*i],    pB);
            qB = fma2(whP1[2*i+1], hP[2*i+1],  qB);
        }
        float a0 = hsum2(add2(pA, qA));
        float a1 = hsum2(add2(pB, qB));
        float v0 = gate_act(a0, s0, m0);
        float v1 = gate_act(a1, L2E, 1.0f);
        float gg = __shfl_xor_sync(0xffffffffu, v0, 16);
        float oo = __shfl_xor_sync(0xffffffffu, v1, 16);
        float cf = half ? oo : v1;
        float ho = half ? v1 : oo;
        c = fmaf(cf, c, v0 * gg);
        h = ho * gate_act(c, 2.0f*L2E, 2.0f);
    };

    // tail: refresh hP from new h; out = post·h + pb (STG); s1 -> svP
    auto tail = [&](int s){
        bcast16(h, hP);
        u64 po = 0ULL, qo = 0ULL, ps = 0ULL, qs = 0ULL;
#pragma unroll
        for (int i = 0; i < 4; i++){
            po = fma2(pwr[2*i],   hP[2*i],   po);
            qo = fma2(pwr[2*i+1], hP[2*i+1], qo);
            ps = fma2(w1r[2*i],   hP[2*i],   ps);
            qs = fma2(w1r[2*i+1], hP[2*i+1], qs);
        }
        float ao = pb + hsum2(add2(po, qo));
        size_t oidx = (size_t)(TT - 1 - s) * DD;
        outp[oidx] = ao;
        outp[oidx + dupoff] = ao;          // unconditional dual store
        float as = hb1v + hsum2(add2(ps, qs));
        as = fmaxf(as, 0.01f*as);          // s1[g], identical on both halves
        bcast16(as, svP);
    };

    // ---- peeled step 0: original Wih against start0 ----
    gates();
    tail(0);

    // ---- in-register weight fusion: wf = wi @ W2, bias += wi . b2 ----
    {
        float wv[16], nf[16];
#pragma unroll
        for (int i = 0; i < 8; i++) unpack2(wiP0[i], wv[2*i], wv[2*i+1]);
        float bc = 0.0f;
#pragma unroll
        for (int j = 0; j < 16; j++) bc = fmaf(wv[j], b2s[j], bc);
#pragma unroll
        for (int k = 0; k < 16; k++){
            float a = 0.0f;
#pragma unroll
            for (int j = 0; j < 16; j++) a = fmaf(wv[j], W2s[j*HH + k], a);
            nf[k] = a;
        }
#pragma unroll
        for (int i = 0; i < 8; i++) wiP0[i] = pack2(nf[2*i], nf[2*i+1]);
        bg0P = pack2(bS0 + bc, 0.0f);

#pragma unroll
        for (int i = 0; i < 8; i++) unpack2(wiP1[i], wv[2*i], wv[2*i+1]);
        bc = 0.0f;
#pragma unroll
        for (int j = 0; j < 16; j++) bc = fmaf(wv[j], b2s[j], bc);
#pragma unroll
        for (int k = 0; k < 16; k++){
            float a = 0.0f;
#pragma unroll
            for (int j = 0; j < 16; j++) a = fmaf(wv[j], W2s[j*HH + k], a);
            nf[k] = a;
        }
#pragma unroll
        for (int i = 0; i < 8; i++) wiP1[i] = pack2(nf[2*i], nf[2*i+1]);
        bg1P = pack2(bS1 + bc, 0.0f);
    }

    // ---- steps 1..511 with fused weights (gates read s1 directly) ----
#pragma unroll 1
    for (int s = 1; s < TT; s++){
        gates();
        tail(s);
    }
}

// ---------------------------------------------------------------------------
extern "C" void kernel_launch(void* const* d_in, const int* in_sizes, int n_in,
                              void* d_out, int out_size)
{
    const float* seq     = (const float*)d_in[0];
    const float* pre_w1  = (const float*)d_in[1];
    const float* pre_b1  = (const float*)d_in[2];
    const float* pre_w2  = (const float*)d_in[3];
    const float* pre_b2  = (const float*)d_in[4];
    const float* pre_w3  = (const float*)d_in[5];
    const float* pre_b3  = (const float*)d_in[6];
    const float* enc_Wih = (const float*)d_in[7];
    const float* enc_Whh = (const float*)d_in[8];
    const float* enc_bih = (const float*)d_in[9];
    const float* enc_bhh = (const float*)d_in[10];
    const float* h2l_w1  = (const float*)d_in[11];
    const float* h2l_b1  = (const float*)d_in[12];
    const float* h2l_w2  = (const float*)d_in[13];
    const float* h2l_b2  = (const float*)d_in[14];
    const float* post_w  = (const float*)d_in[15];
    const float* post_b  = (const float*)d_in[16];

    int dup = (out_size >= 2 * BB * TT * DD) ? 1 : 0;

    prenet_kernel<<<(BB*TT/2)/256, 256>>>(seq, pre_w1, pre_b1, pre_w2, pre_b2, pre_w3, pre_b3);
    encoder_kernel<<<BB/4, 128>>>(enc_Wih, enc_Whh, enc_bih, enc_bhh);
    decoder_kernel<<<BB/4, 128>>>(enc_Wih, enc_Whh, enc_bih, enc_bhh,
                                  h2l_w1, h2l_b1, h2l_w2, h2l_b2,
                                  post_w, post_b, (float*)d_out, dup);
}

// round 17
// speedup vs baseline: 1.0609x; 1.0609x over previous
#include <cuda_runtime.h>

#define BB 2048
#define TT 512
#define DD 32
#define HH 16
typedef unsigned long long u64;

// Scratch (device globals: allocation-guard-safe)
__device__ __align__(16) float g_x[(size_t)TT * BB * HH];   // pre-net output, [t][b][h]
__device__ __align__(16) float g_h[BB * HH];
__device__ __align__(16) float g_c[BB * HH];

__device__ __forceinline__ float ex2f_(float x){ float y; asm("ex2.approx.f32 %0, %1;" : "=f"(y) : "f"(x)); return y; }
__device__ __forceinline__ float rcpf_(float x){ float y; asm("rcp.approx.f32 %0, %1;" : "=f"(y) : "f"(x)); return y; }

#define L2E 1.4426950408889634f

// v = 1 - m * rcp(1 + 2^(s*x)) : sigmoid (s=L2E,m=1), tanh (s=2*L2E,m=2)
__device__ __forceinline__ float gate_act(float x, float s, float m){
    return fmaf(-m, rcpf_(1.0f + ex2f_(s * x)), 1.0f);
}

// ---- f32x2 packed helpers ----
__device__ __forceinline__ u64 pack2(float lo, float hi){ u64 r; asm("mov.b64 %0, {%1,%2};" : "=l"(r) : "f"(lo), "f"(hi)); return r; }
__device__ __forceinline__ u64 dup2(float v){ u64 r; asm("mov.b64 %0, {%1,%1};" : "=l"(r) : "f"(v)); return r; }
__device__ __forceinline__ void unpack2(u64 v, float& lo, float& hi){ asm("mov.b64 {%0,%1}, %2;" : "=f"(lo), "=f"(hi) : "l"(v)); }
__device__ __forceinline__ u64 fma2(u64 a, u64 b, u64 c){ u64 d; asm("fma.rn.f32x2 %0, %1, %2, %3;" : "=l"(d) : "l"(a), "l"(b), "l"(c)); return d; }
__device__ __forceinline__ u64 add2(u64 a, u64 b){ u64 d; asm("add.rn.f32x2 %0, %1, %2;" : "=l"(d) : "l"(a), "l"(b)); return d; }
__device__ __forceinline__ float hsum2(u64 a){ float lo, hi; unpack2(a, lo, hi); return lo + hi; }
__device__ __forceinline__ u64 leaky2(u64 a){
    float lo, hi; unpack2(a, lo, hi);
    lo = fmaxf(lo, 0.01f*lo); hi = fmaxf(hi, 0.01f*hi);
    return pack2(lo, hi);
}

// ---------------------------------------------------------------------------
// Kernel 1: pre-net (85us). 2 rows/thread batch-packed f32x2, scalar smem
// weights (LDS.32 broadcast), k chunked.
// ---------------------------------------------------------------------------
__global__ __launch_bounds__(256) void prenet_kernel(
    const float* __restrict__ seq,
    const float* __restrict__ w1, const float* __restrict__ b1,
    const float* __restrict__ w2, const float* __restrict__ b2,
    const float* __restrict__ w3, const float* __restrict__ b3)
{
    __shared__ float sw1[HH*DD], sw2[HH*HH], sw3[HH*HH], sb[3*HH];
    int tid = threadIdx.x;
    for (int i = tid; i < HH*DD; i += 256) sw1[i] = w1[i];
    for (int i = tid; i < HH*HH; i += 256){ sw2[i] = w2[i]; sw3[i] = w3[i]; }
    if (tid < HH){ sb[tid] = b1[tid]; sb[HH+tid] = b2[tid]; sb[2*HH+tid] = b3[tid]; }
    __syncthreads();

    int r = blockIdx.x * 256 + tid;
    int b = r & (BB - 1);
    int t = r >> 11;

    const float4* rA = reinterpret_cast<const float4*>(seq + ((size_t)b*TT + t)*DD);
    const float4* rB = reinterpret_cast<const float4*>(seq + ((size_t)b*TT + t + 256)*DD);

    u64 acc[HH];
#pragma unroll
    for (int j = 0; j < HH; j++) acc[j] = dup2(sb[j]);

#pragma unroll
    for (int kc = 0; kc < 2; kc++){
        u64 inP[16];
#pragma unroll
        for (int i = 0; i < 4; i++){
            float4 a = rA[kc*4 + i], c = rB[kc*4 + i];
            inP[4*i+0] = pack2(a.x, c.x); inP[4*i+1] = pack2(a.y, c.y);
            inP[4*i+2] = pack2(a.z, c.z); inP[4*i+3] = pack2(a.w, c.w);
        }
#pragma unroll
        for (int j = 0; j < HH; j++){
            const float* wr = &sw1[j*DD + kc*16];
            u64 a = acc[j];
#pragma unroll
            for (int k = 0; k < 16; k++) a = fma2(dup2(wr[k]), inP[k], a);
            acc[j] = a;
        }
    }
    u64 y1[HH];
#pragma unroll
    for (int j = 0; j < HH; j++) y1[j] = leaky2(acc[j]);

#pragma unroll
    for (int j = 0; j < HH; j++){
        const float* wr = &sw2[j*HH];
        u64 a = dup2(sb[HH+j]);
#pragma unroll
        for (int k = 0; k < HH; k++) a = fma2(dup2(wr[k]), y1[k], a);
        acc[j] = a;
    }
    u64 y2[HH];
#pragma unroll
    for (int j = 0; j < HH; j++) y2[j] = leaky2(acc[j]);

    float ya[HH], yb[HH];
#pragma unroll
    for (int j = 0; j < HH; j++){
        const float* wr = &sw3[j*HH];
        u64 a = dup2(sb[2*HH+j]);
#pragma unroll
        for (int k = 0; k < HH; k++) a = fma2(dup2(wr[k]), y2[k], a);
        unpack2(a, ya[j], yb[j]);
    }

    float4* xa = reinterpret_cast<float4*>(g_x + ((size_t)t*BB + b)*HH);
    float4* xb = reinterpret_cast<float4*>(g_x + ((size_t)(t+256)*BB + b)*HH);
#pragma unroll
    for (int i = 0; i < 4; i++){
        xa[i] = make_float4(ya[4*i], ya[4*i+1], ya[4*i+2], ya[4*i+3]);
        xb[i] = make_float4(yb[4*i], yb[4*i+1], yb[4*i+2], yb[4*i+3]);
    }
}

// ---------------------------------------------------------------------------
// Kernel 2: encoder LSTM (R15 structure — best measured). Two elems/warp,
// branch-free loop: symmetric c/h on all lanes + all-lane STS into 32-slot
// padded buffers (no BSSY/BSYNC), 1 syncwarp/step.
// ---------------------------------------------------------------------------
__global__ __launch_bounds__(128) void encoder_kernel(
    const float* __restrict__ Wih, const float* __restrict__ Whh,
    const float* __restrict__ bih, const float* __restrict__ bhh)
{
    __shared__ __align__(16) float hb[4][2][2][32];   // [warp][elem][buf][lane-slot]
    int tid  = threadIdx.x;
    int w    = tid >> 5, lane = tid & 31;
    int g    = lane & 15, half = lane >> 4;
    int b0   = blockIdx.x * 8 + w*2;
    int b1   = b0 + 1;

    int r0 = half ? (2*HH + g) : g;
    int r1 = half ? (3*HH + g) : (HH + g);

    u64 wiP0[8], wiP1[8], whP0[8], whP1[8];
    {
        const ulonglong2* p0 = reinterpret_cast<const ulonglong2*>(Wih + r0*HH);
        const ulonglong2* p1 = reinterpret_cast<const ulonglong2*>(Wih + r1*HH);
        const ulonglong2* q0 = reinterpret_cast<const ulonglong2*>(Whh + r0*HH);
        const ulonglong2* q1 = reinterpret_cast<const ulonglong2*>(Whh + r1*HH);
#pragma unroll
        for (int i = 0; i < 4; i++){
            ulonglong2 v;
            v = p0[i]; wiP0[2*i] = v.x; wiP0[2*i+1] = v.y;
            v = p1[i]; wiP1[2*i] = v.x; wiP1[2*i+1] = v.y;
            v = q0[i]; whP0[2*i] = v.x; whP0[2*i+1] = v.y;
            v = q1[i]; whP1[2*i] = v.x; whP1[2*i+1] = v.y;
        }
    }
    u64 bg0P = pack2(bih[r0] + bhh[r0], 0.0f);
    u64 bg1P = pack2(bih[r1] + bhh[r1], 0.0f);
    float s0 = half ? 2.0f*L2E : L2E;
    float m0 = half ? 2.0f : 1.0f;

    float c0 = 0.0f, h0 = 0.0f, c1 = 0.0f, h1 = 0.0f;
    hb[w][0][0][lane] = 0.0f;
    hb[w][1][0][lane] = 0.0f;

    u64 x0P[8], x1P[8];
    {
        const ulonglong2* p = reinterpret_cast<const ulonglong2*>(g_x + (size_t)b0*HH);
        const ulonglong2* q = reinterpret_cast<const ulonglong2*>(g_x + (size_t)b1*HH);
#pragma unroll
        for (int i = 0; i < 4; i++){
            ulonglong2 v = p[i]; x0P[2*i] = v.x; x0P[2*i+1] = v.y;
            ulonglong2 u = q[i]; x1P[2*i] = u.x; x1P[2*i+1] = u.y;
        }
    }
    __syncwarp();

#pragma unroll 1
    for (int t = 0; t < TT; t++){
        int cur = t & 1, nxt = cur ^ 1;
        const ulonglong2* h0p = reinterpret_cast<const ulonglong2*>(hb[w][0][cur]);
        const ulonglong2* h1p = reinterpret_cast<const ulonglong2*>(hb[w][1][cur]);

        u64 pA0 = bg0P, qA0 = 0ULL, pB0 = bg1P, qB0 = 0ULL;
        u64 pA1 = bg0P, qA1 = 0ULL, pB1 = bg1P, qB1 = 0ULL;
#pragma unroll
        for (int i = 0; i < 4; i++){
            ulonglong2 hv0 = h0p[i], hv1 = h1p[i];
            pA0 = fma2(whP0[2*i],   hv0.x, pA0);  qA0 = fma2(whP0[2*i+1], hv0.y, qA0);
            pB0 = fma2(whP1[2*i],   hv0.x, pB0);  qB0 = fma2(whP1[2*i+1], hv0.y, qB0);
            pA1 = fma2(whP0[2*i],   hv1.x, pA1);  qA1 = fma2(whP0[2*i+1], hv1.y, qA1);
            pB1 = fma2(whP1[2*i],   hv1.x, pB1);  qB1 = fma2(whP1[2*i+1], hv1.y, qB1);
            pA0 = fma2(wiP0[2*i],   x0P[2*i],   pA0);
            qA0 = fma2(wiP0[2*i+1], x0P[2*i+1], qA0);
            pB0 = fma2(wiP1[2*i],   x0P[2*i],   pB0);
            qB0 = fma2(wiP1[2*i+1], x0P[2*i+1], qB0);
            pA1 = fma2(wiP0[2*i],   x1P[2*i],   pA1);
            qA1 = fma2(wiP0[2*i+1], x1P[2*i+1], qA1);
            pB1 = fma2(wiP1[2*i],   x1P[2*i],   pB1);
            qB1 = fma2(wiP1[2*i+1], x1P[2*i+1], qB1);
        }
        {
            int tn = (t + 1 < TT) ? t + 1 : t;
            const ulonglong2* pn = reinterpret_cast<const ulonglong2*>(g_x + ((size_t)tn*BB + b0)*HH);
            const ulonglong2* qn = reinterpret_cast<const ulonglong2*>(g_x + ((size_t)tn*BB + b1)*HH);
#pragma unroll
            for (int i = 0; i < 4; i++){
                ulonglong2 v = pn[i]; x0P[2*i] = v.x; x0P[2*i+1] = v.y;
                ulonglong2 u = qn[i]; x1P[2*i] = u.x; x1P[2*i+1] = u.y;
            }
        }
        float a00 = hsum2(add2(pA0, qA0)), a10 = hsum2(add2(pB0, qB0));
        float a01 = hsum2(add2(pA1, qA1)), a11 = hsum2(add2(pB1, qB1));
        float v00 = gate_act(a00, s0, m0), v10 = gate_act(a10, L2E, 1.0f);
        float v01 = gate_act(a01, s0, m0), v11 = gate_act(a11, L2E, 1.0f);
        float gg0 = __shfl_xor_sync(0xffffffffu, v00, 16);
        float oo0 = __shfl_xor_sync(0xffffffffu, v10, 16);
        float gg1 = __shfl_xor_sync(0xffffffffu, v01, 16);
        float oo1 = __shfl_xor_sync(0xffffffffu, v11, 16);
        float cf0 = half ? oo0 : v10, ho0 = half ? v10 : oo0;
        float cf1 = half ? oo1 : v11, ho1 = half ? v11 : oo1;
        c0 = fmaf(cf0, c0, v00 * gg0);
        c1 = fmaf(cf1, c1, v01 * gg1);
        h0 = ho0 * gate_act(c0, 2.0f*L2E, 2.0f);
        h1 = ho1 * gate_act(c1, 2.0f*L2E, 2.0f);

        hb[w][0][nxt][lane] = h0;      // all-lane store; slots 16-31 are padding
        hb[w][1][nxt][lane] = h1;
        __syncwarp();
    }
    if (!half){
        g_h[b0*HH + g] = h0; g_c[b0*HH + g] = c0;
        g_h[b1*HH + g] = h1; g_c[b1*HH + g] = c1;
    }
}

// ---------------------------------------------------------------------------
// Kernel 3: decoder (R15 structure + CHANGE: loop-invariant tail weight rows
// (post_w row, h2l_w1 row) hoisted from smem into registers — removes 8
// LDS.128 per warp-step of MIO traffic that ptxas left in smem under dual-elem
// pressure). Two elems/warp + W2-fusion + branch-free loop.
// ---------------------------------------------------------------------------
__global__ __launch_bounds__(128) void decoder_kernel(
    const float* __restrict__ Wih, const float* __restrict__ Whh,
    const float* __restrict__ bih, const float* __restrict__ bhh,
    const float* __restrict__ h2l_w1, const float* __restrict__ h2l_b1,
    const float* __restrict__ h2l_w2, const float* __restrict__ h2l_b2,
    const float* __restrict__ post_w, const float* __restrict__ post_b,
    float* __restrict__ out, int dup)
{
    __shared__ float W2s[HH*HH];
    __shared__ float b2s[HH];
    __shared__ __align__(16) float hbuf[4][2][2][32];  // padded, all-lane stores
    __shared__ __align__(16) float s1buf[4][2][32];

    int tid = threadIdx.x;
    for (int i = tid; i < HH*HH; i += 128) W2s[i] = h2l_w2[i];
    if (tid < HH) b2s[tid] = h2l_b2[tid];
    __syncthreads();

    int w    = tid >> 5, lane = tid & 31;
    int g    = lane & 15, half = lane >> 4;
    int b0   = blockIdx.x * 8 + w*2;
    int b1e  = b0 + 1;

    int r0 = half ? (2*HH + g) : g;
    int r1 = half ? (3*HH + g) : (HH + g);

    u64 wiP0[8], wiP1[8], whP0[8], whP1[8];
    {
        const ulonglong2* p0 = reinterpret_cast<const ulonglong2*>(Wih + r0*HH);
        const ulonglong2* p1 = reinterpret_cast<const ulonglong2*>(Wih + r1*HH);
        const ulonglong2* q0 = reinterpret_cast<const ulonglong2*>(Whh + r0*HH);
        const ulonglong2* q1 = reinterpret_cast<const ulonglong2*>(Whh + r1*HH);
#pragma unroll
        for (int i = 0; i < 4; i++){
            ulonglong2 v;
            v = p0[i]; wiP0[2*i] = v.x; wiP0[2*i+1] = v.y;
            v = p1[i]; wiP1[2*i] = v.x; wiP1[2*i+1] = v.y;
            v = q0[i]; whP0[2*i] = v.x; whP0[2*i+1] = v.y;
            v = q1[i]; whP1[2*i] = v.x; whP1[2*i+1] = v.y;
        }
    }
    // Hoisted tail weights: post_w row (lane = output d), h2l_w1 row (g)
    u64 pwR[8], w1R[8];
    {
        const ulonglong2* pw = reinterpret_cast<const ulonglong2*>(post_w + lane*HH);
        const ulonglong2* w1 = reinterpret_cast<const ulonglong2*>(h2l_w1 + g*HH);
#pragma unroll
        for (int i = 0; i < 4; i++){
            ulonglong2 v = pw[i]; pwR[2*i] = v.x; pwR[2*i+1] = v.y;
            ulonglong2 u = w1[i]; w1R[2*i] = u.x; w1R[2*i+1] = u.y;
        }
    }
    float bS0 = bih[r0] + bhh[r0];
    float bS1 = bih[r1] + bhh[r1];
    u64 bg0P = pack2(bS0, 0.0f);
    u64 bg1P = pack2(bS1, 0.0f);
    float s0 = half ? 2.0f*L2E : L2E;
    float m0 = half ? 2.0f : 1.0f;
    float pb  = post_b[lane];
    float hb1v = h2l_b1[g];

    float c0 = g_c[b0*HH + g];
    float c1 = g_c[b1e*HH + g];

    // init smem state (all-lane; duplicate writes across halves are benign)
    hbuf[w][0][0][lane] = g_h[b0*HH + (lane & 15)];
    hbuf[w][1][0][lane] = g_h[b1e*HH + (lane & 15)];
    s1buf[w][0][lane]   = g_x[((size_t)(TT-1)*BB + b0)*HH + (lane & 15)];
    s1buf[w][1][lane]   = g_x[((size_t)(TT-1)*BB + b1e)*HH + (lane & 15)];
    __syncwarp();

    float* outp0 = out + (size_t)b0*TT*DD + lane;
    float* outp1 = out + (size_t)b1e*TT*DD + lane;
    const size_t dupoff = dup ? (size_t)BB*TT*DD : 0;   // dup=0 -> same-address double store (benign)

    // ---- symmetric gates for one elem (all lanes correct; branch-free) ----
    auto gates = [&](const float* svb, const float* hvb, float& c, float& h){
        const ulonglong2* svp = reinterpret_cast<const ulonglong2*>(svb);
        const ulonglong2* hvp = reinterpret_cast<const ulonglong2*>(hvb);
        u64 pA = bg0P, qA = 0ULL, pB = bg1P, qB = 0ULL;
#pragma unroll
        for (int i = 0; i < 4; i++){
            ulonglong2 sv = svp[i];
            ulonglong2 hv = hvp[i];
            pA = fma2(wiP0[2*i],   sv.x, pA);  qA = fma2(wiP0[2*i+1], sv.y, qA);
            pB = fma2(wiP1[2*i],   sv.x, pB);  qB = fma2(wiP1[2*i+1], sv.y, qB);
            pA = fma2(whP0[2*i],   hv.x, pA);  qA = fma2(whP0[2*i+1], hv.y, qA);
            pB = fma2(whP1[2*i],   hv.x, pB);  qB = fma2(whP1[2*i+1], hv.y, qB);
        }
        float a0 = hsum2(add2(pA, qA));
        float a1 = hsum2(add2(pB, qB));
        float v0 = gate_act(a0, s0, m0);
        float v1 = gate_act(a1, L2E, 1.0f);
        float gg = __shfl_xor_sync(0xffffffffu, v0, 16);
        float oo = __shfl_xor_sync(0xffffffffu, v1, 16);
        float cf = half ? oo : v1;
        float ho = half ? v1 : oo;
        c = fmaf(cf, c, v0 * gg);
        h = ho * gate_act(c, 2.0f*L2E, 2.0f);
    };

    // ---- per-step tail: h -> (out, s1) for both elems; register weights ----
    auto tail = [&](int s, int nxt){
        const ulonglong2* h0p = reinterpret_cast<const ulonglong2*>(hbuf[w][0][nxt]);
        const ulonglong2* h1p = reinterpret_cast<const ulonglong2*>(hbuf[w][1][nxt]);
        u64 po0 = 0ULL, qo0 = 0ULL, po1 = 0ULL, qo1 = 0ULL;
        u64 ps0 = 0ULL, qs0 = 0ULL, ps1 = 0ULL, qs1 = 0ULL;
#pragma unroll
        for (int i = 0; i < 4; i++){
            ulonglong2 hv0 = h0p[i], hv1 = h1p[i];
            po0 = fma2(pwR[2*i], hv0.x, po0);  qo0 = fma2(pwR[2*i+1], hv0.y, qo0);
            po1 = fma2(pwR[2*i], hv1.x, po1);  qo1 = fma2(pwR[2*i+1], hv1.y, qo1);
            ps0 = fma2(w1R[2*i], hv0.x, ps0);  qs0 = fma2(w1R[2*i+1], hv0.y, qs0);
            ps1 = fma2(w1R[2*i], hv1.x, ps1);  qs1 = fma2(w1R[2*i+1], hv1.y, qs1);
        }
        float as0 = hb1v + hsum2(add2(ps0, qs0));
        float as1 = hb1v + hsum2(add2(ps1, qs1));
        as0 = fmaxf(as0, 0.01f*as0);
        as1 = fmaxf(as1, 0.01f*as1);
        s1buf[w][0][lane] = as0;        // all-lane (both halves compute identical s1[g])
        s1buf[w][1][lane] = as1;
        float ao0 = pb + hsum2(add2(po0, qo0));
        float ao1 = pb + hsum2(add2(po1, qo1));
        size_t oidx = (size_t)(TT - 1 - s) * DD;
        outp0[oidx] = ao0;
        outp1[oidx] = ao1;
        outp0[oidx + dupoff] = ao0;     // unconditional dual store (no branch)
        outp1[oidx + dupoff] = ao1;
    };

    float h0, h1;

    // ---- peeled step 0: original Wih against start0 ----
    {
        gates(s1buf[w][0], hbuf[w][0][0], c0, h0);
        gates(s1buf[w][1], hbuf[w][1][0], c1, h1);
        hbuf[w][0][1][lane] = h0;
        hbuf[w][1][1][lane] = h1;
        __syncwarp();
        tail(0, 1);
        __syncwarp();
    }

    // ---- in-register weight fusion: wf = wi @ W2, bias += wi . b2 ----
    {
        float wv[16], nf[16];
#pragma unroll
        for (int i = 0; i < 8; i++) unpack2(wiP0[i], wv[2*i], wv[2*i+1]);
        float bc = 0.0f;
#pragma unroll
        for (int j = 0; j < 16; j++) bc = fmaf(wv[j], b2s[j], bc);
#pragma unroll
        for (int k = 0; k < 16; k++){
            float a = 0.0f;
#pragma unroll
            for (int j = 0; j < 16; j++) a = fmaf(wv[j], W2s[j*HH + k], a);
            nf[k] = a;
        }
#pragma unroll
        for (int i = 0; i < 8; i++) wiP0[i] = pack2(nf[2*i], nf[2*i+1]);
        bg0P = pack2(bS0 + bc, 0.0f);

#pragma unroll
        for (int i = 0; i < 8; i++) unpack2(wiP1[i], wv[2*i], wv[2*i+1]);
        bc = 0.0f;
#pragma unroll
        for (int j = 0; j < 16; j++) bc = fmaf(wv[j], b2s[j], bc);
#pragma unroll
        for (int k = 0; k < 16; k++){
            float a = 0.0f;
#pragma unroll
            for (int j = 0; j < 16; j++) a = fmaf(wv[j], W2s[j*HH + k], a);
            nf[k] = a;
        }
#pragma unroll
        for (int i = 0; i < 8; i++) wiP1[i] = pack2(nf[2*i], nf[2*i+1]);
        bg1P = pack2(bS1 + bc, 0.0f);
    }

    // ---- steps 1..511 with fused weights (gates read s1 directly) ----
#pragma unroll 1
    for (int s = 1; s < TT; s++){
        int cur = s & 1, nxt = cur ^ 1;
        gates(s1buf[w][0], hbuf[w][0][cur], c0, h0);
        gates(s1buf[w][1], hbuf[w][1][cur], c1, h1);
        hbuf[w][0][nxt][lane] = h0;
        hbuf[w][1][nxt][lane] = h1;
        __syncwarp();
        tail(s, nxt);
        __syncwarp();
    }
}

// ---------------------------------------------------------------------------
extern "C" void kernel_launch(void* const* d_in, const int* in_sizes, int n_in,
                              void* d_out, int out_size)
{
    const float* seq     = (const float*)d_in[0];
    const float* pre_w1  = (const float*)d_in[1];
    const float* pre_b1  = (const float*)d_in[2];
    const float* pre_w2  = (const float*)d_in[3];
    const float* pre_b2  = (const float*)d_in[4];
    const float* pre_w3  = (const float*)d_in[5];
    const float* pre_b3  = (const float*)d_in[6];
    const float* enc_Wih = (const float*)d_in[7];
    const float* enc_Whh = (const float*)d_in[8];
    const float* enc_bih = (const float*)d_in[9];
    const float* enc_bhh = (const float*)d_in[10];
    const float* h2l_w1  = (const float*)d_in[11];
    const float* h2l_b1  = (const float*)d_in[12];
    const float* h2l_w2  = (const float*)d_in[13];
    const float* h2l_b2  = (const float*)d_in[14];
    const float* post_w  = (const float*)d_in[15];
    const float* post_b  = (const float*)d_in[16];

    int dup = (out_size >= 2 * BB * TT * DD) ? 1 : 0;

    prenet_kernel<<<(BB*TT/2)/256, 256>>>(seq, pre_w1, pre_b1, pre_w2, pre_b2, pre_w3, pre_b3);
    encoder_kernel<<<BB/8, 128>>>(enc_Wih, enc_Whh, enc_bih, enc_bhh);
    decoder_kernel<<<BB/8, 128>>>(enc_Wih, enc_Whh, enc_bih, enc_bhh,
                                  h2l_w1, h2l_b1, h2l_w2, h2l_b2,
                                  post_w, post_b, (float*)d_out, dup);
}